// round 7
// baseline (speedup 1.0000x reference)
#include <cuda_runtime.h>
#include <cstdint>

// GlobalFilter: out = irfft2( rfft2(x,ortho) * W, ortho ), 16x16 spatial, per channel.
//   Ph1: column rDFT over t, f32x2-packed over row pair (r, r+8); x pre-scaled 1/128
//   Ph2: per-(c,v) row circular conv: 16-pt FFT + raw-W pointwise + IFFT (v=1..7)
//        v={0,8} packed real dense conv with precomputed taps (x0.5 scale)
//   Ph3: inverse column pass, f32x2-packed over row pair
//
// x: [128,256,768] f32 ; W: [16,9,768,2] f32 ; out: [128,256,768] f32

#define PP    16
#define NV    9
#define CT    32
#define CCH   768
#define NCT   (CCH / CT)   // 24
#define BPB   4            // batches per block

// real taps for v=0 / v=8 dense conv: [ct][d][c32] -> (mu0, mu8) * 0.5
__device__ float2 g_muR[NCT * PP * CT];

__host__ __device__ __forceinline__ constexpr float C16(int k) {
    return (k % 16 == 0)  ?  1.0f :
           (k % 16 == 1)  ?  0.9238795325112867f :
           (k % 16 == 2)  ?  0.7071067811865476f :
           (k % 16 == 3)  ?  0.3826834323650898f :
           (k % 16 == 4)  ?  0.0f :
           (k % 16 == 5)  ? -0.3826834323650898f :
           (k % 16 == 6)  ? -0.7071067811865476f :
           (k % 16 == 7)  ? -0.9238795325112867f :
           (k % 16 == 8)  ? -1.0f :
           (k % 16 == 9)  ? -0.9238795325112867f :
           (k % 16 == 10) ? -0.7071067811865476f :
           (k % 16 == 11) ? -0.3826834323650898f :
           (k % 16 == 12) ?  0.0f :
           (k % 16 == 13) ?  0.3826834323650898f :
           (k % 16 == 14) ?  0.7071067811865476f :
                             0.9238795325112867f;
}
__host__ __device__ __forceinline__ constexpr float S16(int k) {
    return C16(k % 16 + 12);
}
__host__ __device__ __forceinline__ constexpr int REV4(int i) {
    return ((i & 1) << 3) | ((i & 2) << 1) | ((i & 4) >> 1) | ((i & 8) >> 3);
}

// scalar add/sub as FFMA-imm (rt=1)
__device__ __forceinline__ float fadd1(float a, float b) {
    float r; asm("fma.rn.f32 %0, %1, 0f3F800000, %2;" : "=f"(r) : "f"(a), "f"(b)); return r;
}
__device__ __forceinline__ float fsub1(float a, float b) {  // a - b
    float r; asm("fma.rn.f32 %0, %1, 0fBF800000, %2;" : "=f"(r) : "f"(b), "f"(a)); return r;
}

__device__ __forceinline__ uint64_t pack2(float lo, float hi) {
    uint64_t r; asm("mov.b64 %0, {%1, %2};" : "=l"(r) : "f"(lo), "f"(hi)); return r;
}
__device__ __forceinline__ void unpack2(uint64_t v, float& lo, float& hi) {
    asm("mov.b64 {%0, %1}, %2;" : "=f"(lo), "=f"(hi) : "l"(v));
}
__device__ __forceinline__ uint64_t fma2(uint64_t a, uint64_t b, uint64_t c) {
    uint64_t r; asm("fma.rn.f32x2 %0, %1, %2, %3;" : "=l"(r) : "l"(a), "l"(b), "l"(c)); return r;
}

// packed-constant table: [ +1, +c1, +c2, +c3, -1, -c1, -c2, -c3 ]
struct CPk { uint64_t p[8]; };
__device__ __forceinline__ CPk build_cp() {
    CPk cp;
    const float c1 = 0.9238795325112867f, c2 = 0.7071067811865476f, c3 = 0.3826834323650898f;
    cp.p[0] = pack2(1.0f, 1.0f);  cp.p[1] = pack2(c1, c1);
    cp.p[2] = pack2(c2, c2);      cp.p[3] = pack2(c3, c3);
    cp.p[4] = pack2(-1.0f,-1.0f); cp.p[5] = pack2(-c1,-c1);
    cp.p[6] = pack2(-c2,-c2);     cp.p[7] = pack2(-c3,-c3);
    return cp;
}
// acc += x * C16(K)  (packed); skips when C16(K)==0
template<int K>
__device__ __forceinline__ void accC(uint64_t& acc, uint64_t x, const CPk& cp) {
    constexpr int k = ((K) % 16 + 16) % 16;
    if constexpr (k == 4 || k == 12) { return; }
    else {
        constexpr int cls = (k == 0 || k == 8) ? 0
                          : ((k & 7) == 1 || (k & 7) == 7) ? 1
                          : ((k & 7) == 2 || (k & 7) == 6) ? 2 : 3;
        constexpr bool neg = (k >= 5 && k <= 11);
        acc = fma2(x, cp.p[cls + (neg ? 4 : 0)], acc);
    }
}
__device__ __forceinline__ uint64_t fadd2(uint64_t a, uint64_t b, const CPk& cp) {
    return fma2(a, cp.p[0], b);
}
__device__ __forceinline__ uint64_t fsub2(uint64_t a, uint64_t b, const CPk& cp) { // a-b
    return fma2(b, cp.p[4], a);
}

// complex butterfly
__device__ __forceinline__ void bfly(float& ar, float& ai, float& br, float& bi) {
    float sr = fadd1(ar, br), si = fadd1(ai, bi);
    float dr = fsub1(ar, br), di = fsub1(ai, bi);
    ar = sr; ai = si; br = dr; bi = di;
}
template<int K> __device__ __forceinline__ void twf(float& re, float& im) {
    constexpr int k = ((K) % 16 + 16) % 16;
    if constexpr (k == 0) { }
    else if constexpr (k == 4)  { float t = re; re = im;  im = -t; }
    else if constexpr (k == 8)  { re = -re; im = -im; }
    else if constexpr (k == 12) { float t = re; re = -im; im = t;  }
    else {
        constexpr float cs = C16(k), sn = S16(k);
        float nr = fmaf(im,  sn, re * cs);
        float ni = fmaf(re, -sn, im * cs);
        re = nr; im = ni;
    }
}
template<int K> __device__ __forceinline__ void twi(float& re, float& im) {
    constexpr int k = ((K) % 16 + 16) % 16;
    if constexpr (k == 0) { }
    else if constexpr (k == 4)  { float t = re; re = -im; im = t;  }
    else if constexpr (k == 8)  { re = -re; im = -im; }
    else if constexpr (k == 12) { float t = re; re = im;  im = -t; }
    else {
        constexpr float cs = C16(k), sn = S16(k);
        float nr = fmaf(im, -sn, re * cs);
        float ni = fmaf(re,  sn, im * cs);
        re = nr; im = ni;
    }
}

// 16-pt DIF forward FFT, natural in -> bit-reversed out
__device__ __forceinline__ void fft16_fwd(float* Xr, float* Xi) {
#pragma unroll
    for (int j = 0; j < 8; j++) { bfly(Xr[j], Xi[j], Xr[j+8], Xi[j+8]); }
    twf<1>(Xr[9],Xi[9]);  twf<2>(Xr[10],Xi[10]); twf<3>(Xr[11],Xi[11]);
    twf<4>(Xr[12],Xi[12]); twf<5>(Xr[13],Xi[13]); twf<6>(Xr[14],Xi[14]); twf<7>(Xr[15],Xi[15]);
#pragma unroll
    for (int h = 0; h < 2; h++) {
        int o = h * 8;
#pragma unroll
        for (int j = 0; j < 4; j++) bfly(Xr[o+j], Xi[o+j], Xr[o+j+4], Xi[o+j+4]);
        twf<2>(Xr[o+5],Xi[o+5]); twf<4>(Xr[o+6],Xi[o+6]); twf<6>(Xr[o+7],Xi[o+7]);
    }
#pragma unroll
    for (int q = 0; q < 4; q++) {
        int o = q * 4;
        bfly(Xr[o], Xi[o], Xr[o+2], Xi[o+2]);
        bfly(Xr[o+1], Xi[o+1], Xr[o+3], Xi[o+3]);
        twf<4>(Xr[o+3], Xi[o+3]);
    }
#pragma unroll
    for (int p = 0; p < 8; p++) bfly(Xr[2*p], Xi[2*p], Xr[2*p+1], Xi[2*p+1]);
}

// 16-pt DIT inverse FFT (unscaled), bit-reversed in -> natural out
__device__ __forceinline__ void fft16_inv(float* Xr, float* Xi) {
#pragma unroll
    for (int p = 0; p < 8; p++) bfly(Xr[2*p], Xi[2*p], Xr[2*p+1], Xi[2*p+1]);
#pragma unroll
    for (int q = 0; q < 4; q++) {
        int o = q * 4;
        twi<4>(Xr[o+3], Xi[o+3]);
        bfly(Xr[o], Xi[o], Xr[o+2], Xi[o+2]);
        bfly(Xr[o+1], Xi[o+1], Xr[o+3], Xi[o+3]);
    }
#pragma unroll
    for (int h = 0; h < 2; h++) {
        int o = h * 8;
        twi<2>(Xr[o+5],Xi[o+5]); twi<4>(Xr[o+6],Xi[o+6]); twi<6>(Xr[o+7],Xi[o+7]);
#pragma unroll
        for (int j = 0; j < 4; j++) bfly(Xr[o+j], Xi[o+j], Xr[o+j+4], Xi[o+j+4]);
    }
    twi<1>(Xr[9],Xi[9]);  twi<2>(Xr[10],Xi[10]); twi<3>(Xr[11],Xi[11]);
    twi<4>(Xr[12],Xi[12]); twi<5>(Xr[13],Xi[13]); twi<6>(Xr[14],Xi[14]); twi<7>(Xr[15],Xi[15]);
#pragma unroll
    for (int j = 0; j < 8; j++) bfly(Xr[j], Xi[j], Xr[j+8], Xi[j+8]);
}

// ---------------------------------------------------------------------------
// K1 prep: spatial taps for v in {0,8} only (1536 threads, register IFFT)
// ---------------------------------------------------------------------------
__global__ void gf_prep(const float* __restrict__ w) {
    int tid = blockIdx.x * blockDim.x + threadIdx.x;
    if (tid >= CCH * 2) return;
    int vsel = tid & 1;                 // 0 -> v=0, 1 -> v=8
    int c    = tid >> 1;
    int v    = vsel ? 8 : 0;
    float Zr[16], Zi[16];
#pragma unroll
    for (int u = 0; u < 16; u++) {
        int iw = ((u * NV + v) * CCH + c) * 2;
        int i  = REV4(u);
        Zr[i] = w[iw];
        Zi[i] = w[iw + 1];
    }
    fft16_inv(Zr, Zi);                  // y[d] = sum_u W[u] e^{+2 pi i u d/16}
    int ct = c >> 5;
    int cl = c & (CT - 1);
#pragma unroll
    for (int d = 0; d < 16; d++) {
        float* dst = &g_muR[(ct * PP + d) * CT + cl].x;
        dst[vsel] = Zr[d] * 0.5f;       // (1/256) / (1/128 folded into x)
    }
}

// ---------------------------------------------------------------------------
// K2: block 256 thr, grid (24 c-tiles, 32 batch-quads), 4 batches per block
// ---------------------------------------------------------------------------
__global__ void __launch_bounds__(256, 3) gf_main(const float* __restrict__ x,
                                                  const float* __restrict__ w,
                                                  float* __restrict__ out) {
    __shared__ float2 spec[NV * PP * CT];   // [v][p][c32], reused in-place

    int tid = threadIdx.x;
    int c   = tid & (CT - 1);
    int r   = tid >> 5;                     // 0..7
    int c0  = blockIdx.x * CT;
    int cc  = c;
    int vg  = r;                            // 0 -> packed real (v0,v8); 1..7 -> FFT conv

#pragma unroll 1
    for (int bi = 0; bi < BPB; bi++) {
        int b = blockIdx.y * BPB + bi;

        // ---- Phase 1: packed column rDFT over t for row pair (r, r+8) ----
        {
            CPk cp = build_cp();
            uint64_t k128 = pack2(1.0f/128.0f, 1.0f/128.0f);
            uint64_t xp[16];
            const float* xa = x + ((size_t)(b * 256 + r * 16) * CCH + c0 + c);
            const float* xb = xa + (size_t)8 * 16 * CCH;
#pragma unroll
            for (int t = 0; t < 16; t++) {
                float a = xa[(size_t)t * CCH];
                float bb = xb[(size_t)t * CCH];
                xp[t] = fma2(pack2(a, bb), k128, pack2(0.0f, 0.0f));
            }
            uint64_t sp[8], dp[8];
#pragma unroll
            for (int t = 0; t < 8; t++) {
                sp[t] = fadd2(xp[t], xp[t+8], cp);
                dp[t] = fsub2(xp[t], xp[t+8], cp);
            }
            {   // v = 0 : plain sum
                uint64_t a = fadd2(fadd2(sp[0], sp[1], cp), fadd2(sp[2], sp[3], cp), cp);
                uint64_t bb= fadd2(fadd2(sp[4], sp[5], cp), fadd2(sp[6], sp[7], cp), cp);
                uint64_t re = fadd2(a, bb, cp);
                float lo, hi; unpack2(re, lo, hi);
                spec[(0 * PP + r) * CT + c].x     = lo;
                spec[(0 * PP + r + 8) * CT + c].x = hi;
            }
            {   // v = 8 : alternating sum
                uint64_t a = fadd2(fsub2(sp[0], sp[1], cp), fsub2(sp[2], sp[3], cp), cp);
                uint64_t bb= fadd2(fsub2(sp[4], sp[5], cp), fsub2(sp[6], sp[7], cp), cp);
                uint64_t re = fadd2(a, bb, cp);
                float lo, hi; unpack2(re, lo, hi);
                spec[(8 * PP + r) * CT + c].x     = lo;
                spec[(8 * PP + r + 8) * CT + c].x = hi;
            }
#pragma unroll
            for (int v = 1; v < 8; v++) {
                const uint64_t* src = (v & 1) ? dp : sp;
                uint64_t re = 0ull, im = 0ull;
#pragma unroll
                for (int t = 0; t < 8; t++) {
                    accC<(0*1)>(re, src[t], cp);   // placeholder pattern replaced below
                }
                // (rewritten explicitly to keep v*t compile-time)
                re = 0ull; im = 0ull;
                switch (v) {
                  case 1:
#pragma unroll
                    for (int t = 0; t < 8; t++) { accC<1*0>(re, src[0], cp); break; }
                  default: break;
                }
                // --- generic compile-time expansion ---
                re = 0ull; im = 0ull;
                if (v == 1) {
                    accC<0>(re,src[0],cp); accC<1>(re,src[1],cp); accC<2>(re,src[2],cp); accC<3>(re,src[3],cp);
                    accC<4>(re,src[4],cp); accC<5>(re,src[5],cp); accC<6>(re,src[6],cp); accC<7>(re,src[7],cp);
                    accC<4>(im,src[0],cp); accC<5>(im,src[1],cp); accC<6>(im,src[2],cp); accC<7>(im,src[3],cp);
                    accC<8>(im,src[4],cp); accC<9>(im,src[5],cp); accC<10>(im,src[6],cp); accC<11>(im,src[7],cp);
                } else if (v == 2) {
                    accC<0>(re,src[0],cp); accC<2>(re,src[1],cp); accC<4>(re,src[2],cp); accC<6>(re,src[3],cp);
                    accC<8>(re,src[4],cp); accC<10>(re,src[5],cp); accC<12>(re,src[6],cp); accC<14>(re,src[7],cp);
                    accC<4>(im,src[0],cp); accC<6>(im,src[1],cp); accC<8>(im,src[2],cp); accC<10>(im,src[3],cp);
                    accC<12>(im,src[4],cp); accC<14>(im,src[5],cp); accC<0>(im,src[6],cp); accC<2>(im,src[7],cp);
                } else if (v == 3) {
                    accC<0>(re,src[0],cp); accC<3>(re,src[1],cp); accC<6>(re,src[2],cp); accC<9>(re,src[3],cp);
                    accC<12>(re,src[4],cp); accC<15>(re,src[5],cp); accC<2>(re,src[6],cp); accC<5>(re,src[7],cp);
                    accC<4>(im,src[0],cp); accC<7>(im,src[1],cp); accC<10>(im,src[2],cp); accC<13>(im,src[3],cp);
                    accC<0>(im,src[4],cp); accC<3>(im,src[5],cp); accC<6>(im,src[6],cp); accC<9>(im,src[7],cp);
                } else if (v == 4) {
                    accC<0>(re,src[0],cp); accC<4>(re,src[1],cp); accC<8>(re,src[2],cp); accC<12>(re,src[3],cp);
                    accC<0>(re,src[4],cp); accC<4>(re,src[5],cp); accC<8>(re,src[6],cp); accC<12>(re,src[7],cp);
                    accC<4>(im,src[0],cp); accC<8>(im,src[1],cp); accC<12>(im,src[2],cp); accC<0>(im,src[3],cp);
                    accC<4>(im,src[4],cp); accC<8>(im,src[5],cp); accC<12>(im,src[6],cp); accC<0>(im,src[7],cp);
                } else if (v == 5) {
                    accC<0>(re,src[0],cp); accC<5>(re,src[1],cp); accC<10>(re,src[2],cp); accC<15>(re,src[3],cp);
                    accC<4>(re,src[4],cp); accC<9>(re,src[5],cp); accC<14>(re,src[6],cp); accC<3>(re,src[7],cp);
                    accC<4>(im,src[0],cp); accC<9>(im,src[1],cp); accC<14>(im,src[2],cp); accC<3>(im,src[3],cp);
                    accC<8>(im,src[4],cp); accC<13>(im,src[5],cp); accC<2>(im,src[6],cp); accC<7>(im,src[7],cp);
                } else if (v == 6) {
                    accC<0>(re,src[0],cp); accC<6>(re,src[1],cp); accC<12>(re,src[2],cp); accC<2>(re,src[3],cp);
                    accC<8>(re,src[4],cp); accC<14>(re,src[5],cp); accC<4>(re,src[6],cp); accC<10>(re,src[7],cp);
                    accC<4>(im,src[0],cp); accC<10>(im,src[1],cp); accC<0>(im,src[2],cp); accC<6>(im,src[3],cp);
                    accC<12>(im,src[4],cp); accC<2>(im,src[5],cp); accC<8>(im,src[6],cp); accC<14>(im,src[7],cp);
                } else { // v == 7
                    accC<0>(re,src[0],cp); accC<7>(re,src[1],cp); accC<14>(re,src[2],cp); accC<5>(re,src[3],cp);
                    accC<12>(re,src[4],cp); accC<3>(re,src[5],cp); accC<10>(re,src[6],cp); accC<1>(re,src[7],cp);
                    accC<4>(im,src[0],cp); accC<11>(im,src[1],cp); accC<2>(im,src[2],cp); accC<9>(im,src[3],cp);
                    accC<0>(im,src[4],cp); accC<7>(im,src[5],cp); accC<14>(im,src[6],cp); accC<5>(im,src[7],cp);
                }
                float rlo, rhi, ilo, ihi;
                unpack2(re, rlo, rhi); unpack2(im, ilo, ihi);
                spec[(v * PP + r) * CT + c]     = make_float2(rlo, ilo);
                spec[(v * PP + r + 8) * CT + c] = make_float2(rhi, ihi);
            }
        }
        __syncthreads();

        // ---- Phase 2 ----
        if (vg == 0) {
            uint64_t muA[16];
            {
                const uint64_t* mR = reinterpret_cast<const uint64_t*>(g_muR)
                                   + (blockIdx.x * PP) * CT + cc;
#pragma unroll
                for (int d = 0; d < 16; d++) muA[d] = mR[d * CT];
            }
#pragma unroll
            for (int half = 0; half < 2; half++) {
                uint64_t T[8];
#pragma unroll
                for (int s8 = 0; s8 < 8; s8++) T[s8] = 0ull;
#pragma unroll
                for (int p = 0; p < 16; p++) {
                    float x0 = spec[(0 * PP + p) * CT + cc].x;
                    float x8 = spec[(8 * PP + p) * CT + cc].x;
                    uint64_t XR = pack2(x0, x8);
#pragma unroll
                    for (int s8 = 0; s8 < 8; s8++) {
                        int s = half * 8 + s8;
                        T[s8] = fma2(muA[(s - p) & 15], XR, T[s8]);
                    }
                }
#pragma unroll
                for (int s8 = 0; s8 < 8; s8++) {
                    int s = half * 8 + s8;
                    float t0, t8;
                    unpack2(T[s8], t0, t8);
                    spec[(0 * PP + s) * CT + cc].y = t0;
                    spec[(8 * PP + s) * CT + cc].y = t8;
                }
            }
        } else {
            int v = vg;
            // raw W loads (bit-reversed order), issued early to overlap FFT
            float Wr[16], Wi[16];
            {
                const float2* wb = reinterpret_cast<const float2*>(w) + v * CCH + c0 + cc;
#pragma unroll
                for (int i = 0; i < 16; i++) {
                    float2 t = wb[REV4(i) * NV * CCH];
                    Wr[i] = t.x; Wi[i] = t.y;
                }
            }
            float Xr[16], Xi[16];
#pragma unroll
            for (int p = 0; p < 16; p++) {
                float2 t = spec[(v * PP + p) * CT + cc];
                Xr[p] = t.x; Xi[p] = t.y;
            }
            fft16_fwd(Xr, Xi);
#pragma unroll
            for (int i = 0; i < 16; i++) {
                float nr = fmaf(-Xi[i], Wi[i], Xr[i] * Wr[i]);
                float ni = fmaf( Xi[i], Wr[i], Xr[i] * Wi[i]);
                Xr[i] = nr; Xi[i] = ni;
            }
            fft16_inv(Xr, Xi);
#pragma unroll
            for (int s = 0; s < 16; s++)
                spec[(v * PP + s) * CT + cc] = make_float2(Xr[s], Xi[s]);
        }
        __syncthreads();

        // ---- Phase 3: packed inverse column pass for row pair (r, r+8) ----
        {
            CPk cp = build_cp();
            uint64_t t0p, t8p;
            uint64_t Xp[8], Yp[8];
            {
                float a = spec[(0 * PP + r) * CT + c].y;
                float bb= spec[(0 * PP + r + 8) * CT + c].y;
                t0p = pack2(a, bb);
                a  = spec[(8 * PP + r) * CT + c].y;
                bb = spec[(8 * PP + r + 8) * CT + c].y;
                t8p = pack2(a, bb);
            }
#pragma unroll
            for (int v = 1; v < 8; v++) {
                float2 lo = spec[(v * PP + r) * CT + c];
                float2 hi = spec[(v * PP + r + 8) * CT + c];
                Xp[v] = pack2(lo.x, hi.x);
                Yp[v] = pack2(lo.y, hi.y);
            }
            float* opa = out + ((size_t)(b * 256 + r * 16) * CCH + c0 + c);
            float* opb = opa + (size_t)8 * 16 * CCH;
#pragma unroll
            for (int t = 0; t < 8; t++) {
                uint64_t ge = (t & 1) ? fsub2(t0p, t8p, cp) : fadd2(t0p, t8p, cp);
                uint64_t go = 0ull;
                // even v = 2,4,6 ; odd v = 1,3,5,7 ; ge/go += X*C16(vt) + Y*C16(vt+4)
                switch (t) {
                  case 0:
                    accC<0>(ge,Xp[2],cp); accC<4>(ge,Yp[2],cp);
                    accC<0>(ge,Xp[4],cp); accC<4>(ge,Yp[4],cp);
                    accC<0>(ge,Xp[6],cp); accC<4>(ge,Yp[6],cp);
                    accC<0>(go,Xp[1],cp); accC<4>(go,Yp[1],cp);
                    accC<0>(go,Xp[3],cp); accC<4>(go,Yp[3],cp);
                    accC<0>(go,Xp[5],cp); accC<4>(go,Yp[5],cp);
                    accC<0>(go,Xp[7],cp); accC<4>(go,Yp[7],cp);
                    break;
                  case 1:
                    accC<2>(ge,Xp[2],cp); accC<6>(ge,Yp[2],cp);
                    accC<4>(ge,Xp[4],cp); accC<8>(ge,Yp[4],cp);
                    accC<6>(ge,Xp[6],cp); accC<10>(ge,Yp[6],cp);
                    accC<1>(go,Xp[1],cp); accC<5>(go,Yp[1],cp);
                    accC<3>(go,Xp[3],cp); accC<7>(go,Yp[3],cp);
                    accC<5>(go,Xp[5],cp); accC<9>(go,Yp[5],cp);
                    accC<7>(go,Xp[7],cp); accC<11>(go,Yp[7],cp);
                    break;
                  case 2:
                    accC<4>(ge,Xp[2],cp); accC<8>(ge,Yp[2],cp);
                    accC<8>(ge,Xp[4],cp); accC<12>(ge,Yp[4],cp);
                    accC<12>(ge,Xp[6],cp); accC<0>(ge,Yp[6],cp);
                    accC<2>(go,Xp[1],cp); accC<6>(go,Yp[1],cp);
                    accC<6>(go,Xp[3],cp); accC<10>(go,Yp[3],cp);
                    accC<10>(go,Xp[5],cp); accC<14>(go,Yp[5],cp);
                    accC<14>(go,Xp[7],cp); accC<2>(go,Yp[7],cp);
                    break;
                  case 3:
                    accC<6>(ge,Xp[2],cp); accC<10>(ge,Yp[2],cp);
                    accC<12>(ge,Xp[4],cp); accC<0>(ge,Yp[4],cp);
                    accC<2>(ge,Xp[6],cp); accC<6>(ge,Yp[6],cp);
                    accC<3>(go,Xp[1],cp); accC<7>(go,Yp[1],cp);
                    accC<9>(go,Xp[3],cp); accC<13>(go,Yp[3],cp);
                    accC<15>(go,Xp[5],cp); accC<3>(go,Yp[5],cp);
                    accC<5>(go,Xp[7],cp); accC<9>(go,Yp[7],cp);
                    break;
                  case 4:
                    accC<8>(ge,Xp[2],cp); accC<12>(ge,Yp[2],cp);
                    accC<0>(ge,Xp[4],cp); accC<4>(ge,Yp[4],cp);
                    accC<8>(ge,Xp[6],cp); accC<12>(ge,Yp[6],cp);
                    accC<4>(go,Xp[1],cp); accC<8>(go,Yp[1],cp);
                    accC<12>(go,Xp[3],cp); accC<0>(go,Yp[3],cp);
                    accC<4>(go,Xp[5],cp); accC<8>(go,Yp[5],cp);
                    accC<12>(go,Xp[7],cp); accC<0>(go,Yp[7],cp);
                    break;
                  case 5:
                    accC<10>(ge,Xp[2],cp); accC<14>(ge,Yp[2],cp);
                    accC<4>(ge,Xp[4],cp); accC<8>(ge,Yp[4],cp);
                    accC<14>(ge,Xp[6],cp); accC<2>(ge,Yp[6],cp);
                    accC<5>(go,Xp[1],cp); accC<9>(go,Yp[1],cp);
                    accC<15>(go,Xp[3],cp); accC<3>(go,Yp[3],cp);
                    accC<9>(go,Xp[5],cp); accC<13>(go,Yp[5],cp);
                    accC<3>(go,Xp[7],cp); accC<7>(go,Yp[7],cp);
                    break;
                  case 6:
                    accC<12>(ge,Xp[2],cp); accC<0>(ge,Yp[2],cp);
                    accC<8>(ge,Xp[4],cp); accC<12>(ge,Yp[4],cp);
                    accC<4>(ge,Xp[6],cp); accC<8>(ge,Yp[6],cp);
                    accC<6>(go,Xp[1],cp); accC<10>(go,Yp[1],cp);
                    accC<2>(go,Xp[3],cp); accC<6>(go,Yp[3],cp);
                    accC<14>(go,Xp[5],cp); accC<2>(go,Yp[5],cp);
                    accC<10>(go,Xp[7],cp); accC<14>(go,Yp[7],cp);
                    break;
                  default: // t == 7
                    accC<14>(ge,Xp[2],cp); accC<2>(ge,Yp[2],cp);
                    accC<12>(ge,Xp[4],cp); accC<0>(ge,Yp[4],cp);
                    accC<10>(ge,Xp[6],cp); accC<14>(ge,Yp[6],cp);
                    accC<7>(go,Xp[1],cp); accC<11>(go,Yp[1],cp);
                    accC<5>(go,Xp[3],cp); accC<9>(go,Yp[3],cp);
                    accC<3>(go,Xp[5],cp); accC<7>(go,Yp[5],cp);
                    accC<1>(go,Xp[7],cp); accC<5>(go,Yp[7],cp);
                    break;
                }
                uint64_t oa = fadd2(ge, go, cp);
                uint64_t ob = fsub2(ge, go, cp);
                float alo, ahi, blo, bhi;
                unpack2(oa, alo, ahi); unpack2(ob, blo, bhi);
                opa[(size_t)t * CCH]       = alo;
                opa[(size_t)(t + 8) * CCH] = blo;
                opb[(size_t)t * CCH]       = ahi;
                opb[(size_t)(t + 8) * CCH] = bhi;
            }
        }
        __syncthreads();   // spec reused by next batch's phase 1
    }
}

// ---------------------------------------------------------------------------
extern "C" void kernel_launch(void* const* d_in, const int* in_sizes, int n_in,
                              void* d_out, int out_size) {
    const float* x = (const float*)d_in[0];
    const float* w = (const float*)d_in[1];
    float* out     = (float*)d_out;
    (void)in_sizes; (void)n_in; (void)out_size;

    gf_prep<<<(CCH * 2 + 255) / 256, 256>>>(w);

    dim3 grid(NCT, 128 / BPB);
    gf_main<<<grid, 256>>>(x, w, out);
}